// round 2
// baseline (speedup 1.0000x reference)
#include <cuda_runtime.h>
#include <math.h>

#define T_LEN 8192
#define THREADS_SCAN 512
#define NWARPS (THREADS_SCAN / 32)       // 16
#define PER (T_LEN / THREADS_SCAN)       // 16 elements per thread
#define DISCOUNT 0.99f
#define EPS 1e-9f
#define MAX_ROWS 8192

__device__ float g_rowsum[MAX_ROWS];
__device__ float g_rowinv[MAX_ROWS];
__device__ float g_mean;

// ---------------------------------------------------------------------------
// K1: per-row reverse affine scan + per-row stats (shuffle-based, 3 barriers)
// ret[t] = r[t] + g[t]*ret[t+1],  g[t] = DISCOUNT*(1-done[t])
// Reversed index s = T-1-t -> forward recurrence y = a*y + b.
// Thread j owns reversed positions [j*PER,(j+1)*PER) = contiguous 64B chunk.
// ---------------------------------------------------------------------------
__global__ __launch_bounds__(THREADS_SCAN)
void scan_kernel(const float* __restrict__ rew,
                 const float* __restrict__ done,
                 float* __restrict__ out)
{
    const int b = blockIdx.x;
    const size_t rowoff = (size_t)b * T_LEN;
    const float* r = rew + rowoff;
    const float* d = done + rowoff;
    float* o = out + rowoff;

    const int j    = threadIdx.x;
    const int lane = j & 31;
    const int warp = j >> 5;
    const int tbase = T_LEN - PER * (j + 1);

    float rv[PER];
    float av[PER];

#pragma unroll
    for (int k = 0; k < PER / 4; k++) {
        float4 rr = *(const float4*)(r + tbase + 4 * k);
        float4 dd = *(const float4*)(d + tbase + 4 * k);
        rv[4 * k + 0] = rr.x; av[4 * k + 0] = DISCOUNT * (1.0f - dd.x);
        rv[4 * k + 1] = rr.y; av[4 * k + 1] = DISCOUNT * (1.0f - dd.y);
        rv[4 * k + 2] = rr.z; av[4 * k + 2] = DISCOUNT * (1.0f - dd.z);
        rv[4 * k + 3] = rr.w; av[4 * k + 3] = DISCOUNT * (1.0f - dd.w);
    }

    // Compose this thread's affine map, applying elements in s-ascending order
    // (t descending). Split into two independent chains for latency, then join.
    //   high half: i = 15..8 (applied first), low half: i = 7..0 (applied after)
    float Ah = 1.0f, Bh = 0.0f, Al = 1.0f, Bl = 0.0f;
#pragma unroll
    for (int i = PER - 1; i >= PER / 2; i--) {
        Bh = fmaf(av[i], Bh, rv[i]);
        Ah = av[i] * Ah;
    }
#pragma unroll
    for (int i = PER / 2 - 1; i >= 0; i--) {
        Bl = fmaf(av[i], Bl, rv[i]);
        Al = av[i] * Al;
    }
    // total = low ∘ high
    float A = Al * Ah;
    float B = fmaf(Al, Bh, Bl);

    // Intra-warp inclusive affine scan (5 shfl steps, no barriers).
    // combine(left(a1,b1), self(A,B)): B = A*b1 + B ; A = A*a1
#pragma unroll
    for (int off = 1; off < 32; off <<= 1) {
        float a1 = __shfl_up_sync(0xffffffffu, A, off);
        float b1 = __shfl_up_sync(0xffffffffu, B, off);
        if (lane >= off) {
            B = fmaf(A, b1, B);
            A = A * a1;
        }
    }

    // Exclusive-within-warp map for this thread
    float Ae = __shfl_up_sync(0xffffffffu, A, 1);
    float Be = __shfl_up_sync(0xffffffffu, B, 1);
    if (lane == 0) { Ae = 1.0f; Be = 0.0f; }

    __shared__ float sWA[NWARPS];
    __shared__ float sWB[NWARPS];
    __shared__ float sWP[NWARPS];        // warp-prefix B (inclusive)
    __shared__ float sRS[NWARPS];
    __shared__ float sRQ[NWARPS];

    if (lane == 31) { sWA[warp] = A; sWB[warp] = B; }
    __syncthreads();

    // Warp 0 scans the 16 warp aggregates
    if (warp == 0) {
        float a = (lane < NWARPS) ? sWA[lane] : 1.0f;
        float bb = (lane < NWARPS) ? sWB[lane] : 0.0f;
#pragma unroll
        for (int off = 1; off < NWARPS; off <<= 1) {
            float a1 = __shfl_up_sync(0xffffffffu, a, off);
            float b1 = __shfl_up_sync(0xffffffffu, bb, off);
            if (lane >= off) {
                bb = fmaf(a, b1, bb);
                a = a * a1;
            }
        }
        if (lane < NWARPS) sWP[lane] = bb;
    }
    __syncthreads();

    // Incoming value for this thread: y_in = Ae * Bw + Be  (y0 = 0)
    const float Bw = (warp == 0) ? 0.0f : sWP[warp - 1];
    float y = fmaf(Ae, Bw, Be);

    // Rematerialize outputs from registers, accumulate stats
    float ov[PER];
    float lsum = 0.0f, lsq = 0.0f;
#pragma unroll
    for (int i = PER - 1; i >= 0; i--) {
        y = fmaf(av[i], y, rv[i]);
        ov[i] = y;
        lsum += y;
        lsq  = fmaf(y, y, lsq);
    }

#pragma unroll
    for (int k = 0; k < PER / 4; k++) {
        float4 w;
        w.x = ov[4 * k + 0];
        w.y = ov[4 * k + 1];
        w.z = ov[4 * k + 2];
        w.w = ov[4 * k + 3];
        *(float4*)(o + tbase + 4 * k) = w;
    }

    // Deterministic block reduction: shuffle within warp, then warp 0.
#pragma unroll
    for (int off = 16; off > 0; off >>= 1) {
        lsum += __shfl_down_sync(0xffffffffu, lsum, off);
        lsq  += __shfl_down_sync(0xffffffffu, lsq,  off);
    }
    if (lane == 0) { sRS[warp] = lsum; sRQ[warp] = lsq; }
    __syncthreads();
    if (warp == 0) {
        float s = (lane < NWARPS) ? sRS[lane] : 0.0f;
        float q = (lane < NWARPS) ? sRQ[lane] : 0.0f;
#pragma unroll
        for (int off = 8; off > 0; off >>= 1) {
            s += __shfl_down_sync(0xffffffffu, s, off);
            q += __shfl_down_sync(0xffffffffu, q, off);
        }
        if (lane == 0) {
            g_rowsum[b] = s;
            float var = (q - s * s * (1.0f / T_LEN)) * (1.0f / (T_LEN - 1));
            var = fmaxf(var, 0.0f);
            g_rowinv[b] = 1.0f / (sqrtf(var) + EPS);
        }
    }
}

// ---------------------------------------------------------------------------
// K2: deterministic reduction of row sums -> global mean
// ---------------------------------------------------------------------------
__global__ __launch_bounds__(1024)
void mean_kernel(int n_rows)
{
    __shared__ double sd[1024];
    const int j = threadIdx.x;
    double acc = 0.0;
    for (int i = j; i < n_rows; i += 1024)
        acc += (double)g_rowsum[i];
    sd[j] = acc;
    __syncthreads();
#pragma unroll
    for (int off = 512; off > 0; off >>= 1) {
        if (j < off) sd[j] += sd[j + off];
        __syncthreads();
    }
    if (j == 0)
        g_mean = (float)(sd[0] / ((double)n_rows * (double)T_LEN));
}

// ---------------------------------------------------------------------------
// K3: in-place normalize  out = (out - mean) * rowinv[b]
// ---------------------------------------------------------------------------
__global__ __launch_bounds__(256)
void norm_kernel(float* __restrict__ out, int n4)
{
    const float mean = g_mean;
    int i = blockIdx.x * blockDim.x + threadIdx.x;
    if (i >= n4) return;
    float4 v = ((const float4*)out)[i];
    const int row = (i * 4) >> 13;           // /T_LEN, T=8192
    const float inv = g_rowinv[row];
    v.x = (v.x - mean) * inv;
    v.y = (v.y - mean) * inv;
    v.z = (v.z - mean) * inv;
    v.w = (v.w - mean) * inv;
    ((float4*)out)[i] = v;
}

extern "C" void kernel_launch(void* const* d_in, const int* in_sizes, int n_in,
                              void* d_out, int out_size)
{
    const float* rewards = (const float*)d_in[0];
    const float* dones   = (const float*)d_in[1];
    float* out = (float*)d_out;

    const int n = in_sizes[0];
    const int B = n / T_LEN;

    scan_kernel<<<B, THREADS_SCAN>>>(rewards, dones, out);
    mean_kernel<<<1, 1024>>>(B);
    const int n4 = n / 4;
    norm_kernel<<<(n4 + 255) / 256, 256>>>(out, n4);
}

// round 3
// speedup vs baseline: 1.3480x; 1.3480x over previous
#include <cuda_runtime.h>
#include <math.h>

#define T_LEN 8192
#define THREADS_SCAN 512
#define NWARPS (THREADS_SCAN / 32)       // 16
#define PER (T_LEN / THREADS_SCAN)       // 16 elements per thread
#define DISCOUNT 0.99f
#define EPS 1e-9f
#define MAX_ROWS 8192

__device__ float g_rowsum[MAX_ROWS];
__device__ float g_rowinv[MAX_ROWS];
__device__ float g_mean;

// ---------------------------------------------------------------------------
// K1: per-row reverse affine scan + per-row stats.
// ret[t] = r[t] + g[t]*ret[t+1],  g[t] = DISCOUNT*(1-done[t]), done binary.
// Thread j owns original t range [T-PER*(j+1), T-PER*j) (contiguous 64B),
// processed in t-descending order (= scan order).
// done flags packed into a 16-bit mask; outputs streamed (no ov[] array).
// ---------------------------------------------------------------------------
__global__ __launch_bounds__(THREADS_SCAN)
void scan_kernel(const float* __restrict__ rew,
                 const float* __restrict__ done,
                 float* __restrict__ out)
{
    const int b = blockIdx.x;
    const size_t rowoff = (size_t)b * T_LEN;
    const float* r = rew + rowoff;
    const float* d = done + rowoff;
    float* o = out + rowoff;

    const int j    = threadIdx.x;
    const int lane = j & 31;
    const int warp = j >> 5;
    const int tbase = T_LEN - PER * (j + 1);

    float rv[PER];
    unsigned mask = 0;   // bit i set -> done at local index i

#pragma unroll
    for (int k = 0; k < PER / 4; k++) {
        float4 rr = *(const float4*)(r + tbase + 4 * k);
        float4 dd = *(const float4*)(d + tbase + 4 * k);
        rv[4 * k + 0] = rr.x;
        rv[4 * k + 1] = rr.y;
        rv[4 * k + 2] = rr.z;
        rv[4 * k + 3] = rr.w;
        if (dd.x != 0.0f) mask |= (1u << (4 * k + 0));
        if (dd.y != 0.0f) mask |= (1u << (4 * k + 1));
        if (dd.z != 0.0f) mask |= (1u << (4 * k + 2));
        if (dd.w != 0.0f) mask |= (1u << (4 * k + 3));
    }

    // Compose this thread's affine map y_out = A*y_in + B, applying elements
    // in t-descending order (i = PER-1 .. 0). Element i:
    //   done:  A' = 0,       B' = r_i
    //   else:  A' = 0.99*A,  B' = 0.99*B + r_i
    // Two independent half-chains for ILP, then join: total = low ∘ high.
    float Ah = 1.0f, Bh = 0.0f, Al = 1.0f, Bl = 0.0f;
#pragma unroll
    for (int i = PER - 1; i >= PER / 2; i--) {
        const bool dn = (mask >> i) & 1u;
        Bh = dn ? rv[i] : fmaf(DISCOUNT, Bh, rv[i]);
        Ah = dn ? 0.0f  : DISCOUNT * Ah;
    }
#pragma unroll
    for (int i = PER / 2 - 1; i >= 0; i--) {
        const bool dn = (mask >> i) & 1u;
        Bl = dn ? rv[i] : fmaf(DISCOUNT, Bl, rv[i]);
        Al = dn ? 0.0f  : DISCOUNT * Al;
    }
    float A = Al * Ah;
    float B = fmaf(Al, Bh, Bl);

    // Intra-warp inclusive affine scan (5 shfl steps).
#pragma unroll
    for (int off = 1; off < 32; off <<= 1) {
        float a1 = __shfl_up_sync(0xffffffffu, A, off);
        float b1 = __shfl_up_sync(0xffffffffu, B, off);
        if (lane >= off) {
            B = fmaf(A, b1, B);
            A = A * a1;
        }
    }

    // Exclusive-within-warp map for this thread
    float Ae = __shfl_up_sync(0xffffffffu, A, 1);
    float Be = __shfl_up_sync(0xffffffffu, B, 1);
    if (lane == 0) { Ae = 1.0f; Be = 0.0f; }

    __shared__ float sWA[NWARPS];
    __shared__ float sWB[NWARPS];
    __shared__ float sWP[NWARPS];
    __shared__ float sRS[NWARPS];
    __shared__ float sRQ[NWARPS];

    if (lane == 31) { sWA[warp] = A; sWB[warp] = B; }
    __syncthreads();

    if (warp == 0) {
        float a  = (lane < NWARPS) ? sWA[lane] : 1.0f;
        float bb = (lane < NWARPS) ? sWB[lane] : 0.0f;
#pragma unroll
        for (int off = 1; off < NWARPS; off <<= 1) {
            float a1 = __shfl_up_sync(0xffffffffu, a, off);
            float b1 = __shfl_up_sync(0xffffffffu, bb, off);
            if (lane >= off) {
                bb = fmaf(a, b1, bb);
                a = a * a1;
            }
        }
        if (lane < NWARPS) sWP[lane] = bb;
    }
    __syncthreads();

    // Incoming value: y_in = Ae * Bw + Be  (row starts from y0 = 0)
    const float Bw = (warp == 0) ? 0.0f : sWP[warp - 1];
    float y = fmaf(Ae, Bw, Be);

    // Rematerialize + store on the fly (i descending, stores per float4 group)
    float lsum = 0.0f, lsq = 0.0f;
#pragma unroll
    for (int k = PER / 4 - 1; k >= 0; k--) {
        float4 w;
        {
            const bool dn = (mask >> (4 * k + 3)) & 1u;
            y = dn ? rv[4 * k + 3] : fmaf(DISCOUNT, y, rv[4 * k + 3]);
            w.w = y; lsum += y; lsq = fmaf(y, y, lsq);
        }
        {
            const bool dn = (mask >> (4 * k + 2)) & 1u;
            y = dn ? rv[4 * k + 2] : fmaf(DISCOUNT, y, rv[4 * k + 2]);
            w.z = y; lsum += y; lsq = fmaf(y, y, lsq);
        }
        {
            const bool dn = (mask >> (4 * k + 1)) & 1u;
            y = dn ? rv[4 * k + 1] : fmaf(DISCOUNT, y, rv[4 * k + 1]);
            w.y = y; lsum += y; lsq = fmaf(y, y, lsq);
        }
        {
            const bool dn = (mask >> (4 * k + 0)) & 1u;
            y = dn ? rv[4 * k + 0] : fmaf(DISCOUNT, y, rv[4 * k + 0]);
            w.x = y; lsum += y; lsq = fmaf(y, y, lsq);
        }
        *(float4*)(o + tbase + 4 * k) = w;
    }

    // Deterministic block reduction of sum / sumsq
#pragma unroll
    for (int off = 16; off > 0; off >>= 1) {
        lsum += __shfl_down_sync(0xffffffffu, lsum, off);
        lsq  += __shfl_down_sync(0xffffffffu, lsq,  off);
    }
    if (lane == 0) { sRS[warp] = lsum; sRQ[warp] = lsq; }
    __syncthreads();
    if (warp == 0) {
        float s = (lane < NWARPS) ? sRS[lane] : 0.0f;
        float q = (lane < NWARPS) ? sRQ[lane] : 0.0f;
#pragma unroll
        for (int off = 8; off > 0; off >>= 1) {
            s += __shfl_down_sync(0xffffffffu, s, off);
            q += __shfl_down_sync(0xffffffffu, q, off);
        }
        if (lane == 0) {
            g_rowsum[b] = s;
            float var = (q - s * s * (1.0f / T_LEN)) * (1.0f / (T_LEN - 1));
            var = fmaxf(var, 0.0f);
            g_rowinv[b] = 1.0f / (sqrtf(var) + EPS);
        }
    }
}

// ---------------------------------------------------------------------------
// K2: deterministic reduction of row sums -> global mean
// ---------------------------------------------------------------------------
__global__ __launch_bounds__(1024)
void mean_kernel(int n_rows)
{
    __shared__ double sd[1024];
    const int j = threadIdx.x;
    double acc = 0.0;
    for (int i = j; i < n_rows; i += 1024)
        acc += (double)g_rowsum[i];
    sd[j] = acc;
    __syncthreads();
#pragma unroll
    for (int off = 512; off > 0; off >>= 1) {
        if (j < off) sd[j] += sd[j + off];
        __syncthreads();
    }
    if (j == 0)
        g_mean = (float)(sd[0] / ((double)n_rows * (double)T_LEN));
}

// ---------------------------------------------------------------------------
// K3: in-place normalize  out = (out - mean) * rowinv[b]
// ---------------------------------------------------------------------------
__global__ __launch_bounds__(256)
void norm_kernel(float* __restrict__ out, int n4)
{
    const float mean = g_mean;
    int i = blockIdx.x * blockDim.x + threadIdx.x;
    if (i >= n4) return;
    float4 v = ((const float4*)out)[i];
    const int row = (i * 4) >> 13;           // /T_LEN, T=8192
    const float inv = g_rowinv[row];
    v.x = (v.x - mean) * inv;
    v.y = (v.y - mean) * inv;
    v.z = (v.z - mean) * inv;
    v.w = (v.w - mean) * inv;
    ((float4*)out)[i] = v;
}

extern "C" void kernel_launch(void* const* d_in, const int* in_sizes, int n_in,
                              void* d_out, int out_size)
{
    const float* rewards = (const float*)d_in[0];
    const float* dones   = (const float*)d_in[1];
    float* out = (float*)d_out;

    const int n = in_sizes[0];
    const int B = n / T_LEN;

    scan_kernel<<<B, THREADS_SCAN>>>(rewards, dones, out);
    mean_kernel<<<1, 1024>>>(B);
    const int n4 = n / 4;
    norm_kernel<<<(n4 + 255) / 256, 256>>>(out, n4);
}

// round 4
// speedup vs baseline: 1.5709x; 1.1653x over previous
#include <cuda_runtime.h>
#include <math.h>

#define T_LEN 8192
#define THREADS_SCAN 1024
#define NWARPS (THREADS_SCAN / 32)       // 32
#define PER (T_LEN / THREADS_SCAN)       // 8 elements per thread
#define DISCOUNT 0.99f
#define EPS 1e-9f
#define MAX_ROWS 8192

__device__ float g_rowsum[MAX_ROWS];
__device__ float g_rowinv[MAX_ROWS];
__device__ float g_mean;

// ---------------------------------------------------------------------------
// K1: per-row reverse affine scan + per-row stats.
// ret[t] = r[t] + g[t]*ret[t+1],  g[t] = DISCOUNT*(1-done[t]), done binary.
// 1024 threads/row, 8 elems/thread (32B chunks) -> ~30 regs, 2 blocks/SM.
// Inputs loaded with .cs (streaming) to keep L2 free for the output, which
// K3 re-reads.
// ---------------------------------------------------------------------------
__global__ __launch_bounds__(THREADS_SCAN, 2)
void scan_kernel(const float* __restrict__ rew,
                 const float* __restrict__ done,
                 float* __restrict__ out)
{
    const int b = blockIdx.x;
    const size_t rowoff = (size_t)b * T_LEN;
    const float* r = rew + rowoff;
    const float* d = done + rowoff;
    float* o = out + rowoff;

    const int j    = threadIdx.x;
    const int lane = j & 31;
    const int warp = j >> 5;
    const int tbase = T_LEN - PER * (j + 1);

    float rv[PER];
    unsigned mask = 0;   // bit i set -> done at local index i

#pragma unroll
    for (int k = 0; k < PER / 4; k++) {
        float4 rr = __ldcs((const float4*)(r + tbase) + k);
        float4 dd = __ldcs((const float4*)(d + tbase) + k);
        rv[4 * k + 0] = rr.x;
        rv[4 * k + 1] = rr.y;
        rv[4 * k + 2] = rr.z;
        rv[4 * k + 3] = rr.w;
        if (dd.x != 0.0f) mask |= (1u << (4 * k + 0));
        if (dd.y != 0.0f) mask |= (1u << (4 * k + 1));
        if (dd.z != 0.0f) mask |= (1u << (4 * k + 2));
        if (dd.w != 0.0f) mask |= (1u << (4 * k + 3));
    }

    // Compose this thread's affine map y_out = A*y_in + B, applying elements
    // in t-descending order (i = PER-1 .. 0):
    //   done:  A' = 0,       B' = r_i
    //   else:  A' = 0.99*A,  B' = 0.99*B + r_i
    float A = 1.0f, B = 0.0f;
#pragma unroll
    for (int i = PER - 1; i >= 0; i--) {
        const bool dn = (mask >> i) & 1u;
        B = dn ? rv[i] : fmaf(DISCOUNT, B, rv[i]);
        A = dn ? 0.0f  : DISCOUNT * A;
    }

    // Intra-warp inclusive affine scan (5 shfl steps).
#pragma unroll
    for (int off = 1; off < 32; off <<= 1) {
        float a1 = __shfl_up_sync(0xffffffffu, A, off);
        float b1 = __shfl_up_sync(0xffffffffu, B, off);
        if (lane >= off) {
            B = fmaf(A, b1, B);
            A = A * a1;
        }
    }

    // Exclusive-within-warp map for this thread
    float Ae = __shfl_up_sync(0xffffffffu, A, 1);
    float Be = __shfl_up_sync(0xffffffffu, B, 1);
    if (lane == 0) { Ae = 1.0f; Be = 0.0f; }

    __shared__ float sWA[NWARPS];
    __shared__ float sWB[NWARPS];
    __shared__ float sWP[NWARPS];
    __shared__ float sRS[NWARPS];
    __shared__ float sRQ[NWARPS];

    if (lane == 31) { sWA[warp] = A; sWB[warp] = B; }
    __syncthreads();

    // Warp 0 scans the 32 warp aggregates
    if (warp == 0) {
        float a  = sWA[lane];
        float bb = sWB[lane];
#pragma unroll
        for (int off = 1; off < 32; off <<= 1) {
            float a1 = __shfl_up_sync(0xffffffffu, a, off);
            float b1 = __shfl_up_sync(0xffffffffu, bb, off);
            if (lane >= off) {
                bb = fmaf(a, b1, bb);
                a = a * a1;
            }
        }
        sWP[lane] = bb;
    }
    __syncthreads();

    // Incoming value: y_in = Ae * Bw + Be  (row starts from y0 = 0)
    const float Bw = (warp == 0) ? 0.0f : sWP[warp - 1];
    float y = fmaf(Ae, Bw, Be);

    // Rematerialize + store on the fly (i descending, one float4 per group)
    float lsum = 0.0f, lsq = 0.0f;
#pragma unroll
    for (int k = PER / 4 - 1; k >= 0; k--) {
        float4 w;
        {
            const bool dn = (mask >> (4 * k + 3)) & 1u;
            y = dn ? rv[4 * k + 3] : fmaf(DISCOUNT, y, rv[4 * k + 3]);
            w.w = y; lsum += y; lsq = fmaf(y, y, lsq);
        }
        {
            const bool dn = (mask >> (4 * k + 2)) & 1u;
            y = dn ? rv[4 * k + 2] : fmaf(DISCOUNT, y, rv[4 * k + 2]);
            w.z = y; lsum += y; lsq = fmaf(y, y, lsq);
        }
        {
            const bool dn = (mask >> (4 * k + 1)) & 1u;
            y = dn ? rv[4 * k + 1] : fmaf(DISCOUNT, y, rv[4 * k + 1]);
            w.y = y; lsum += y; lsq = fmaf(y, y, lsq);
        }
        {
            const bool dn = (mask >> (4 * k + 0)) & 1u;
            y = dn ? rv[4 * k + 0] : fmaf(DISCOUNT, y, rv[4 * k + 0]);
            w.x = y; lsum += y; lsq = fmaf(y, y, lsq);
        }
        *((float4*)(o + tbase) + k) = w;   // default policy: keep in L2 for K3
    }

    // Deterministic block reduction of sum / sumsq
#pragma unroll
    for (int off = 16; off > 0; off >>= 1) {
        lsum += __shfl_down_sync(0xffffffffu, lsum, off);
        lsq  += __shfl_down_sync(0xffffffffu, lsq,  off);
    }
    if (lane == 0) { sRS[warp] = lsum; sRQ[warp] = lsq; }
    __syncthreads();
    if (warp == 0) {
        float s = sRS[lane];
        float q = sRQ[lane];
#pragma unroll
        for (int off = 16; off > 0; off >>= 1) {
            s += __shfl_down_sync(0xffffffffu, s, off);
            q += __shfl_down_sync(0xffffffffu, q, off);
        }
        if (lane == 0) {
            g_rowsum[b] = s;
            float var = (q - s * s * (1.0f / T_LEN)) * (1.0f / (T_LEN - 1));
            var = fmaxf(var, 0.0f);
            g_rowinv[b] = 1.0f / (sqrtf(var) + EPS);
        }
    }
}

// ---------------------------------------------------------------------------
// K2: deterministic reduction of row sums -> global mean
// ---------------------------------------------------------------------------
__global__ __launch_bounds__(1024)
void mean_kernel(int n_rows)
{
    __shared__ double sd[1024];
    const int j = threadIdx.x;
    double acc = 0.0;
    for (int i = j; i < n_rows; i += 1024)
        acc += (double)g_rowsum[i];
    sd[j] = acc;
    __syncthreads();
#pragma unroll
    for (int off = 512; off > 0; off >>= 1) {
        if (j < off) sd[j] += sd[j + off];
        __syncthreads();
    }
    if (j == 0)
        g_mean = (float)(sd[0] / ((double)n_rows * (double)T_LEN));
}

// ---------------------------------------------------------------------------
// K3: in-place normalize  out = (out - mean) * rowinv[b].
// Blocks mapped in REVERSE address order: K1 wrote high rows last, so they
// are L2-resident; the first norm wave reads them before eviction.
// 4 float4 per thread.
// ---------------------------------------------------------------------------
#define NORM_IPT 4
__global__ __launch_bounds__(256)
void norm_kernel(float* __restrict__ out, int n4)
{
    const float mean = g_mean;
    const int chunk = gridDim.x - 1 - blockIdx.x;      // reversed mapping
    const int base = chunk * (256 * NORM_IPT);
#pragma unroll
    for (int it = 0; it < NORM_IPT; it++) {
        const int i = base + it * 256 + threadIdx.x;
        if (i >= n4) continue;
        float4 v = ((const float4*)out)[i];
        const int row = (i * 4) >> 13;                 // /T_LEN, T=8192
        const float inv = g_rowinv[row];
        v.x = (v.x - mean) * inv;
        v.y = (v.y - mean) * inv;
        v.z = (v.z - mean) * inv;
        v.w = (v.w - mean) * inv;
        __stcs(((float4*)out) + i, v);                 // final write, evict-first
    }
}

extern "C" void kernel_launch(void* const* d_in, const int* in_sizes, int n_in,
                              void* d_out, int out_size)
{
    const float* rewards = (const float*)d_in[0];
    const float* dones   = (const float*)d_in[1];
    float* out = (float*)d_out;

    const int n = in_sizes[0];
    const int B = n / T_LEN;

    scan_kernel<<<B, THREADS_SCAN>>>(rewards, dones, out);
    mean_kernel<<<1, 1024>>>(B);
    const int n4 = n / 4;
    const int nblocks = (n4 + 256 * NORM_IPT - 1) / (256 * NORM_IPT);
    norm_kernel<<<nblocks, 256>>>(out, n4);
}

// round 5
// speedup vs baseline: 1.7102x; 1.0887x over previous
#include <cuda_runtime.h>
#include <math.h>

#define T_LEN 8192
#define THREADS_SCAN 1024
#define NWARPS (THREADS_SCAN / 32)       // 32
#define PER (T_LEN / THREADS_SCAN)       // 8 elements per thread
#define DISCOUNT 0.99f
#define EPS 1e-9f
#define MAX_ROWS 4096                    // B = 4096 in this problem

__device__ float g_rowsum[MAX_ROWS];
__device__ float g_rowinv[MAX_ROWS];
__device__ float g_mean;
// Per-thread replay state: incoming carry + packed done mask (8 bits used)
__device__ float         g_carry[MAX_ROWS * THREADS_SCAN];   // 16 MB
__device__ unsigned char g_mask [MAX_ROWS * THREADS_SCAN];   //  4 MB

// ---------------------------------------------------------------------------
// P1: per-row reverse affine scan -> per-thread carry + per-row stats.
// ret[t] = r[t] + g[t]*ret[t+1],  g[t] = DISCOUNT*(1-done[t]), done binary.
// Does NOT write the 128MB returns array; P2 replays from carry+mask.
// ---------------------------------------------------------------------------
__global__ __launch_bounds__(THREADS_SCAN, 2)
void scan_stats_kernel(const float* __restrict__ rew,
                       const float* __restrict__ done)
{
    const int b = blockIdx.x;
    const size_t rowoff = (size_t)b * T_LEN;
    const float* r = rew + rowoff;
    const float* d = done + rowoff;

    const int j    = threadIdx.x;
    const int lane = j & 31;
    const int warp = j >> 5;
    const int tbase = T_LEN - PER * (j + 1);

    float rv[PER];
    unsigned mask = 0;   // bit i set -> done at local index i

#pragma unroll
    for (int k = 0; k < PER / 4; k++) {
        float4 rr = __ldcs((const float4*)(r + tbase) + k);
        float4 dd = __ldcs((const float4*)(d + tbase) + k);
        rv[4 * k + 0] = rr.x;
        rv[4 * k + 1] = rr.y;
        rv[4 * k + 2] = rr.z;
        rv[4 * k + 3] = rr.w;
        if (dd.x != 0.0f) mask |= (1u << (4 * k + 0));
        if (dd.y != 0.0f) mask |= (1u << (4 * k + 1));
        if (dd.z != 0.0f) mask |= (1u << (4 * k + 2));
        if (dd.w != 0.0f) mask |= (1u << (4 * k + 3));
    }

    // Compose this thread's affine map y_out = A*y_in + B (t-descending):
    //   done:  A' = 0,       B' = r_i
    //   else:  A' = 0.99*A,  B' = 0.99*B + r_i
    float A = 1.0f, B = 0.0f;
#pragma unroll
    for (int i = PER - 1; i >= 0; i--) {
        const bool dn = (mask >> i) & 1u;
        B = dn ? rv[i] : fmaf(DISCOUNT, B, rv[i]);
        A = dn ? 0.0f  : DISCOUNT * A;
    }

    // Intra-warp inclusive affine scan.
#pragma unroll
    for (int off = 1; off < 32; off <<= 1) {
        float a1 = __shfl_up_sync(0xffffffffu, A, off);
        float b1 = __shfl_up_sync(0xffffffffu, B, off);
        if (lane >= off) {
            B = fmaf(A, b1, B);
            A = A * a1;
        }
    }

    // Exclusive-within-warp map for this thread
    float Ae = __shfl_up_sync(0xffffffffu, A, 1);
    float Be = __shfl_up_sync(0xffffffffu, B, 1);
    if (lane == 0) { Ae = 1.0f; Be = 0.0f; }

    __shared__ float sWA[NWARPS];
    __shared__ float sWB[NWARPS];
    __shared__ float sWP[NWARPS];
    __shared__ float sRS[NWARPS];
    __shared__ float sRQ[NWARPS];

    if (lane == 31) { sWA[warp] = A; sWB[warp] = B; }
    __syncthreads();

    if (warp == 0) {
        float a  = sWA[lane];
        float bb = sWB[lane];
#pragma unroll
        for (int off = 1; off < 32; off <<= 1) {
            float a1 = __shfl_up_sync(0xffffffffu, a, off);
            float b1 = __shfl_up_sync(0xffffffffu, bb, off);
            if (lane >= off) {
                bb = fmaf(a, b1, bb);
                a = a * a1;
            }
        }
        sWP[lane] = bb;
    }
    __syncthreads();

    // Incoming value for this thread (row starts from y0 = 0)
    const float Bw = (warp == 0) ? 0.0f : sWP[warp - 1];
    const float yin = fmaf(Ae, Bw, Be);

    // Persist replay state for P2
    const size_t sidx = (size_t)b * THREADS_SCAN + j;
    g_carry[sidx] = yin;
    g_mask[sidx]  = (unsigned char)mask;

    // Rematerialize for stats only (same fma order as P2 replay)
    float y = yin;
    float lsum = 0.0f, lsq = 0.0f;
#pragma unroll
    for (int i = PER - 1; i >= 0; i--) {
        const bool dn = (mask >> i) & 1u;
        y = dn ? rv[i] : fmaf(DISCOUNT, y, rv[i]);
        lsum += y;
        lsq  = fmaf(y, y, lsq);
    }

    // Deterministic block reduction of sum / sumsq
#pragma unroll
    for (int off = 16; off > 0; off >>= 1) {
        lsum += __shfl_down_sync(0xffffffffu, lsum, off);
        lsq  += __shfl_down_sync(0xffffffffu, lsq,  off);
    }
    if (lane == 0) { sRS[warp] = lsum; sRQ[warp] = lsq; }
    __syncthreads();
    if (warp == 0) {
        float s = sRS[lane];
        float q = sRQ[lane];
#pragma unroll
        for (int off = 16; off > 0; off >>= 1) {
            s += __shfl_down_sync(0xffffffffu, s, off);
            q += __shfl_down_sync(0xffffffffu, q, off);
        }
        if (lane == 0) {
            g_rowsum[b] = s;
            float var = (q - s * s * (1.0f / T_LEN)) * (1.0f / (T_LEN - 1));
            var = fmaxf(var, 0.0f);
            g_rowinv[b] = 1.0f / (sqrtf(var) + EPS);
        }
    }
}

// ---------------------------------------------------------------------------
// K2: deterministic reduction of row sums -> global mean
// ---------------------------------------------------------------------------
__global__ __launch_bounds__(1024)
void mean_kernel(int n_rows)
{
    __shared__ double sd[1024];
    const int j = threadIdx.x;
    double acc = 0.0;
    for (int i = j; i < n_rows; i += 1024)
        acc += (double)g_rowsum[i];
    sd[j] = acc;
    __syncthreads();
#pragma unroll
    for (int off = 512; off > 0; off >>= 1) {
        if (j < off) sd[j] += sd[j + off];
        __syncthreads();
    }
    if (j == 0)
        g_mean = (float)(sd[0] / ((double)n_rows * (double)T_LEN));
}

// ---------------------------------------------------------------------------
// P2: barrier-free replay + normalize + store.
// Each thread independently: reload its 8 rewards, carry, mask; replay the
// identical fma chain (bitwise-same returns as the stats pass); write
// (y - mean) * rowinv[b].
// ---------------------------------------------------------------------------
__global__ __launch_bounds__(THREADS_SCAN, 2)
void finalize_kernel(const float* __restrict__ rew,
                     float* __restrict__ out)
{
    const int b = blockIdx.x;
    const size_t rowoff = (size_t)b * T_LEN;
    const float* r = rew + rowoff;
    float* o = out + rowoff;

    const int j = threadIdx.x;
    const int tbase = T_LEN - PER * (j + 1);

    const size_t sidx = (size_t)b * THREADS_SCAN + j;
    float y = g_carry[sidx];
    const unsigned mask = g_mask[sidx];
    const float mean = g_mean;
    const float inv  = g_rowinv[b];

    float rv[PER];
#pragma unroll
    for (int k = 0; k < PER / 4; k++) {
        float4 rr = __ldcs((const float4*)(r + tbase) + k);
        rv[4 * k + 0] = rr.x;
        rv[4 * k + 1] = rr.y;
        rv[4 * k + 2] = rr.z;
        rv[4 * k + 3] = rr.w;
    }

#pragma unroll
    for (int k = PER / 4 - 1; k >= 0; k--) {
        float4 w;
        {
            const bool dn = (mask >> (4 * k + 3)) & 1u;
            y = dn ? rv[4 * k + 3] : fmaf(DISCOUNT, y, rv[4 * k + 3]);
            w.w = (y - mean) * inv;
        }
        {
            const bool dn = (mask >> (4 * k + 2)) & 1u;
            y = dn ? rv[4 * k + 2] : fmaf(DISCOUNT, y, rv[4 * k + 2]);
            w.z = (y - mean) * inv;
        }
        {
            const bool dn = (mask >> (4 * k + 1)) & 1u;
            y = dn ? rv[4 * k + 1] : fmaf(DISCOUNT, y, rv[4 * k + 1]);
            w.y = (y - mean) * inv;
        }
        {
            const bool dn = (mask >> (4 * k + 0)) & 1u;
            y = dn ? rv[4 * k + 0] : fmaf(DISCOUNT, y, rv[4 * k + 0]);
            w.x = (y - mean) * inv;
        }
        __stcs((float4*)(o + tbase) + k, w);
    }
}

extern "C" void kernel_launch(void* const* d_in, const int* in_sizes, int n_in,
                              void* d_out, int out_size)
{
    const float* rewards = (const float*)d_in[0];
    const float* dones   = (const float*)d_in[1];
    float* out = (float*)d_out;

    const int n = in_sizes[0];
    const int B = n / T_LEN;

    scan_stats_kernel<<<B, THREADS_SCAN>>>(rewards, dones);
    mean_kernel<<<1, 1024>>>(B);
    finalize_kernel<<<B, THREADS_SCAN>>>(rewards, out);
}